// round 2
// baseline (speedup 1.0000x reference)
#include <cuda_runtime.h>

// AUCM loss: loss = mean over PxN pairs of (1 - (p_i - n_j))^2 + 1.0 * relu(1 - (p_i - n_j))
//
// Strategy: compact positives & negatives (atomic counters into __device__
// scratch), then brute-force only the ~18.6M real pairs (P*Nn), not the
// 268M masked pairs the reference computes. Pair kernel holds 8 positives
// in registers per block-iteration and loads negatives as float4 for
// 32 pairs (≈96 fma-pipe ops) per LDG.128.

#define MAXN 16384
#define PT 8            // positives per block-iteration (register tile)
#define NTHREADS 256
#define NBLOCKS_PAIRS 1184   // 148 SMs * 8

__device__ float  g_pos[MAXN];
__device__ float  g_neg[MAXN];
__device__ int    g_cnt[2];     // [0] = nP, [1] = nN
__device__ double g_sum;

__global__ void k_init() {
    g_cnt[0] = 0;
    g_cnt[1] = 0;
    g_sum = 0.0;
}

__global__ void k_partition(const float* __restrict__ preds,
                            const int* __restrict__ targets, int n) {
    int i = blockIdx.x * blockDim.x + threadIdx.x;
    if (i < n) {
        float p = preds[i];
        if (targets[i] == 1) {
            int idx = atomicAdd(&g_cnt[0], 1);
            g_pos[idx] = p;
        } else {
            int idx = atomicAdd(&g_cnt[1], 1);
            g_neg[idx] = p;
        }
    }
}

__device__ __forceinline__ void pair_terms(float u, float& acc) {
    acc = fmaf(u, u, acc);       // (1 - (p - n))^2
    acc += fmaxf(u, 0.0f);       // margin * relu, margin = 1
}

__global__ void __launch_bounds__(NTHREADS) k_pairs() {
    const int nP = g_cnt[0];
    const int nN = g_cnt[1];
    const int nN4 = nN & ~3;     // vectorizable prefix
    float acc = 0.0f;

    for (int base = blockIdx.x * PT; base < nP; base += gridDim.x * PT) {
        int rem = nP - base;
        if (rem >= PT) {
            float p1[PT];
            #pragma unroll
            for (int k = 0; k < PT; k++) p1[k] = 1.0f - g_pos[base + k];

            // float4 main loop over negatives
            for (int j = threadIdx.x * 4; j < nN4; j += NTHREADS * 4) {
                float4 nv = *reinterpret_cast<const float4*>(&g_neg[j]);
                #pragma unroll
                for (int k = 0; k < PT; k++) {
                    pair_terms(p1[k] + nv.x, acc);
                    pair_terms(p1[k] + nv.y, acc);
                    pair_terms(p1[k] + nv.z, acc);
                    pair_terms(p1[k] + nv.w, acc);
                }
            }
            // scalar tail (< 4 negatives)
            for (int j = nN4 + threadIdx.x; j < nN; j += NTHREADS) {
                float nj = g_neg[j];
                #pragma unroll
                for (int k = 0; k < PT; k++) pair_terms(p1[k] + nj, acc);
            }
        } else {
            // remainder positive tile (at most one block per sweep)
            float p1[PT];
            for (int k = 0; k < rem; k++) p1[k] = 1.0f - g_pos[base + k];
            for (int j = threadIdx.x; j < nN; j += NTHREADS) {
                float nj = g_neg[j];
                for (int k = 0; k < rem; k++) pair_terms(p1[k] + nj, acc);
            }
        }
    }

    // block reduction
    __shared__ float red[NTHREADS];
    red[threadIdx.x] = acc;
    __syncthreads();
    #pragma unroll
    for (int s = NTHREADS / 2; s > 0; s >>= 1) {
        if (threadIdx.x < s) red[threadIdx.x] += red[threadIdx.x + s];
        __syncthreads();
    }
    if (threadIdx.x == 0 && red[0] != 0.0f)
        atomicAdd(&g_sum, (double)red[0]);
}

__global__ void k_final(float* out) {
    double np = (double)g_cnt[0] * (double)g_cnt[1];
    out[0] = (float)(g_sum / np);
}

extern "C" void kernel_launch(void* const* d_in, const int* in_sizes, int n_in,
                              void* d_out, int out_size) {
    const float* preds   = (const float*)d_in[0];
    const int*   targets = (const int*)d_in[1];
    float*       out     = (float*)d_out;
    int n = in_sizes[0];

    k_init<<<1, 1>>>();
    k_partition<<<(n + NTHREADS - 1) / NTHREADS, NTHREADS>>>(preds, targets, n);
    k_pairs<<<NBLOCKS_PAIRS, NTHREADS>>>();
    k_final<<<1, 1>>>(out);
}

// round 4
// speedup vs baseline: 1.7378x; 1.7378x over previous
#include <cuda_runtime.h>

// AUCM loss, single persistent kernel.
// loss = [ closed-form squared term + pairwise relu term ] / (nP*nN)
//   sum_{ij} (a_i+n_j)^2 = nN*S_aa + 2*S_a*S_n + nP*S_nn   (a_i = 1-p_i)
//   relu term sum_{ij} max(0, a_i+n_j) brute-forced over real pairs only.
//
// Phase 1: warp-aggregated compaction of pos/neg + block-reduced moment sums.
// Software grid barrier (all 592 CTAs resident via __launch_bounds__(256,4)).
// Phase 2: relu pair sum, 8-positive register tile x 4 negative chunks.
// Last-done block finalizes and RESETS all device state for the next replay.

#define MAXN 16384
#define PT 8
#define NT 256
#define GRID 592   // 148 SMs * 4, all resident in one wave
#define JC 4       // negative-chunk split per positive tile

__device__ float  g_pos[MAXN];
__device__ float  g_neg[MAXN];
__device__ int    g_cnt[2];
__device__ double g_Sa, g_Saa, g_Sn, g_Snn, g_relu;
__device__ int    g_arrive, g_done;

__global__ void __launch_bounds__(NT, 4)
k_fused(const float* __restrict__ preds, const int* __restrict__ targets,
        int n, float* __restrict__ out) {
    const int tid  = threadIdx.x;
    const int lane = tid & 31;
    const int wid  = tid >> 5;
    const int gtid = blockIdx.x * NT + tid;

    __shared__ float s_mom[4][NT / 32];   // per-warp moment partials
    __shared__ float s_red[NT / 32];      // phase-2 reduction

    // ---------------- Phase 1: partition + moments ----------------
    if (blockIdx.x * NT < n) {
        bool valid = gtid < n;
        float p = 0.0f; int t = -1;
        if (valid) { p = preds[gtid]; t = targets[gtid]; }
        bool is_pos = valid && (t == 1);
        bool is_neg = valid && (t == 0);
        unsigned mp = __ballot_sync(0xFFFFFFFFu, is_pos);
        unsigned mn = __ballot_sync(0xFFFFFFFFu, is_neg);

        if (is_pos) {
            int rank   = __popc(mp & ((1u << lane) - 1u));
            int leader = __ffs(mp) - 1;
            int base = 0;
            if (lane == leader) base = atomicAdd(&g_cnt[0], __popc(mp));
            base = __shfl_sync(mp, base, leader);
            g_pos[base + rank] = p;
        }
        if (is_neg) {
            int rank   = __popc(mn & ((1u << lane) - 1u));
            int leader = __ffs(mn) - 1;
            int base = 0;
            if (lane == leader) base = atomicAdd(&g_cnt[1], __popc(mn));
            base = __shfl_sync(mn, base, leader);
            g_neg[base + rank] = p;
        }

        float a  = is_pos ? (1.0f - p) : 0.0f;
        float nv = is_neg ? p : 0.0f;
        float sa = a, saa = a * a, sn = nv, snn = nv * nv;
        #pragma unroll
        for (int off = 16; off; off >>= 1) {
            sa  += __shfl_xor_sync(0xFFFFFFFFu, sa,  off);
            saa += __shfl_xor_sync(0xFFFFFFFFu, saa, off);
            sn  += __shfl_xor_sync(0xFFFFFFFFu, sn,  off);
            snn += __shfl_xor_sync(0xFFFFFFFFu, snn, off);
        }
        if (lane == 0) {
            s_mom[0][wid] = sa;  s_mom[1][wid] = saa;
            s_mom[2][wid] = sn;  s_mom[3][wid] = snn;
        }
        __syncthreads();
        if (tid < 4) {
            float v = 0.0f;
            #pragma unroll
            for (int i = 0; i < NT / 32; i++) v += s_mom[tid][i];
            double* dst = (tid == 0) ? &g_Sa : (tid == 1) ? &g_Saa
                        : (tid == 2) ? &g_Sn : &g_Snn;
            atomicAdd(dst, (double)v);
        }
    }

    // ---------------- Grid barrier (all CTAs resident) ----------------
    __threadfence();
    __syncthreads();
    if (tid == 0) {
        atomicAdd(&g_arrive, 1);
        while (*(volatile int*)&g_arrive < GRID) __nanosleep(64);
    }
    __syncthreads();
    __threadfence();

    // ---------------- Phase 2: relu pair sum ----------------
    const int nP = g_cnt[0];
    const int nN = g_cnt[1];
    const int nTiles = (nP + PT - 1) / PT;

    float acc[PT] = {};
    for (int w = blockIdx.x; w < nTiles * JC; w += GRID) {
        int tp = w / JC;
        int jc = w - tp * JC;
        int pb = tp * PT;
        float p1[PT];
        #pragma unroll
        for (int k = 0; k < PT; k++)
            p1[k] = (pb + k < nP) ? (1.0f - g_pos[pb + k]) : -3.0e38f; // sentinel -> relu 0

        for (int j = jc * NT + tid; j < nN; j += JC * NT) {
            float nj = g_neg[j];
            #pragma unroll
            for (int k = 0; k < PT; k++)
                acc[k] += fmaxf(p1[k] + nj, 0.0f);   // 8 independent chains
        }
    }
    float t0 = (acc[0] + acc[1]) + (acc[2] + acc[3]);
    float t1 = (acc[4] + acc[5]) + (acc[6] + acc[7]);
    float th = t0 + t1;

    #pragma unroll
    for (int off = 16; off; off >>= 1) th += __shfl_xor_sync(0xFFFFFFFFu, th, off);
    if (lane == 0) s_red[wid] = th;
    __syncthreads();
    if (tid == 0) {
        float bs = 0.0f;
        #pragma unroll
        for (int i = 0; i < NT / 32; i++) bs += s_red[i];
        if (bs != 0.0f) atomicAdd(&g_relu, (double)bs);
        __threadfence();
        int old = atomicAdd(&g_done, 1);
        if (old == GRID - 1) {
            // all blocks done: finalize + reset state for the next replay
            __threadfence();
            double Sa  = *(volatile double*)&g_Sa;
            double Saa = *(volatile double*)&g_Saa;
            double Sn  = *(volatile double*)&g_Sn;
            double Snn = *(volatile double*)&g_Snn;
            double R   = *(volatile double*)&g_relu;
            double dP = (double)nP, dN = (double)nN;
            double sq = dN * Saa + 2.0 * Sa * Sn + dP * Snn;
            out[0] = (float)((sq + R) / (dP * dN));
            g_cnt[0] = 0; g_cnt[1] = 0;
            g_Sa = 0.0; g_Saa = 0.0; g_Sn = 0.0; g_Snn = 0.0; g_relu = 0.0;
            g_arrive = 0; g_done = 0;
            __threadfence();
        }
    }
}

extern "C" void kernel_launch(void* const* d_in, const int* in_sizes, int n_in,
                              void* d_out, int out_size) {
    const float* preds   = (const float*)d_in[0];
    const int*   targets = (const int*)d_in[1];
    float*       out     = (float*)d_out;
    int n = in_sizes[0];

    k_fused<<<GRID, NT>>>(preds, targets, n, out);
}